// round 8
// baseline (speedup 1.0000x reference)
#include <cuda_runtime.h>
#include <cstdint>

// SubsetOperator: relaxed top-K (K=16, tau=1) via iterative masked softmax.
// Exp-domain: a_i = exp(s_i) * prod(1 - onehot). Moment trick: block-reduce
// (P=Sum a, Q=Sum a^2) once per TWO softmax iterations (S' = P - Q/P), with
// both iterations fused into one quartic sweep:
//   khot += c1*a + c2*a^2,  a'' = a + d2*a^2 + d3*a^3 + d4*a^4
// Two rows per CTA: one barrier/shfl round serves 4 reduced values (P,Q for
// both rows), halving serial reduction overhead per unit of work.

static constexpr int THREADS = 256;
static constexpr int VPT     = 4;            // float4 per thread per row
static constexpr int PAIRS   = VPT * 2;      // 8 f32x2 pairs per row
static constexpr int NCOL    = 4096;
static constexpr int ROUNDS  = 8;            // 2 softmax iters per round = 16
static constexpr int NWARPS  = THREADS / 32;

__device__ __forceinline__ uint64_t pack2(float lo, float hi) {
    uint64_t r; asm("mov.b64 %0, {%1, %2};" : "=l"(r) : "f"(lo), "f"(hi)); return r;
}
__device__ __forceinline__ void unpack2(uint64_t v, float& lo, float& hi) {
    asm("mov.b64 {%0, %1}, %2;" : "=f"(lo), "=f"(hi) : "l"(v));
}
#define FMA2(d, a, b, c) asm("fma.rn.f32x2 %0, %1, %2, %3;" : "=l"(d) : "l"(a), "l"(b), "l"(c))
#define MUL2(d, a, b)    asm("mul.rn.f32x2 %0, %1, %2;"     : "=l"(d) : "l"(a), "l"(b))
#define ADD2(d, a, b)    asm("add.rn.f32x2 %0, %1, %2;"     : "=l"(d) : "l"(a), "l"(b))
#define RCPA(d, s)       asm("rcp.approx.f32 %0, %1;"       : "=f"(d) : "f"(s))

__global__ __launch_bounds__(THREADS, 2) void subset_op_kernel(
    const float* __restrict__ scores,
    const float* __restrict__ gnoise,
    float* __restrict__ out)
{
    __shared__ float4 wred[2][NWARPS];   // (PA, QA, PB, QB) partials, dbl-buffered

    const int tid  = threadIdx.x;
    const int lane = tid & 31;
    const int wid  = tid >> 5;
    const size_t offA = (size_t)(blockIdx.x * 2 + 0) * NCOL;
    const size_t offB = (size_t)(blockIdx.x * 2 + 1) * NCOL;

    const float4* sA4 = reinterpret_cast<const float4*>(scores + offA);
    const float4* gA4 = reinterpret_cast<const float4*>(gnoise + offA);
    const float4* sB4 = reinterpret_cast<const float4*>(scores + offB);
    const float4* gB4 = reinterpret_cast<const float4*>(gnoise + offB);

    uint64_t aA[PAIRS], kA[PAIRS];
    uint64_t aB[PAIRS], kB[PAIRS];
    const uint64_t zero2 = pack2(0.f, 0.f);

    // ---- load both rows, a = exp(scores + g); no max-subtraction needed
    //      (args < ~30, far below fp32 exp overflow; softmax scale-invariant);
    //      first (P, Q) partials per row ----
    float pA = 0.f, qA = 0.f, pB = 0.f, qB = 0.f;
#pragma unroll
    for (int v = 0; v < VPT; v++) {
        float4 sv = sA4[tid + v * THREADS];
        float4 gv = gA4[tid + v * THREADS];
        float e0 = __expf(sv.x + gv.x), e1 = __expf(sv.y + gv.y);
        float e2 = __expf(sv.z + gv.z), e3 = __expf(sv.w + gv.w);
        aA[2*v+0] = pack2(e0, e1); aA[2*v+1] = pack2(e2, e3);
        kA[2*v+0] = zero2;         kA[2*v+1] = zero2;
        pA += e0 + e1 + e2 + e3;
        qA = fmaf(e0,e0,qA); qA = fmaf(e1,e1,qA);
        qA = fmaf(e2,e2,qA); qA = fmaf(e3,e3,qA);

        float4 sw = sB4[tid + v * THREADS];
        float4 gw = gB4[tid + v * THREADS];
        float f0 = __expf(sw.x + gw.x), f1 = __expf(sw.y + gw.y);
        float f2 = __expf(sw.z + gw.z), f3 = __expf(sw.w + gw.w);
        aB[2*v+0] = pack2(f0, f1); aB[2*v+1] = pack2(f2, f3);
        kB[2*v+0] = zero2;         kB[2*v+1] = zero2;
        pB += f0 + f1 + f2 + f3;
        qB = fmaf(f0,f0,qB); qB = fmaf(f1,f1,qB);
        qB = fmaf(f2,f2,qB); qB = fmaf(f3,f3,qB);
    }

    // ---- 8 rounds; each = one 4-value block reduce + fused 2-iter sweep/row ----
#pragma unroll 1
    for (int r = 0; r < ROUNDS; r++) {
        const int buf = r & 1;
        float v0 = pA, v1 = qA, v2 = pB, v3 = qB;
#pragma unroll
        for (int o = 16; o; o >>= 1) {
            v0 += __shfl_xor_sync(0xffffffffu, v0, o);
            v1 += __shfl_xor_sync(0xffffffffu, v1, o);
            v2 += __shfl_xor_sync(0xffffffffu, v2, o);
            v3 += __shfl_xor_sync(0xffffffffu, v3, o);
        }
        if (lane == 0) wred[buf][wid] = make_float4(v0, v1, v2, v3);
        __syncthreads();
        float PA = wred[buf][0].x, QA = wred[buf][0].y;
        float PB = wred[buf][0].z, QB = wred[buf][0].w;
#pragma unroll
        for (int i = 1; i < NWARPS; i++) {
            float4 w = wred[buf][i];
            PA += w.x; QA += w.y; PB += w.z; QB += w.w;
        }
        // no second barrier: next round writes the other buffer

        // per-row 2-step coefficients
        float i1A, i2A, i1B, i2B;
        RCPA(i1A, PA);
        RCPA(i1B, PB);
        float S2A = fmaf(-QA, i1A, PA);
        float S2B = fmaf(-QB, i1B, PB);
        RCPA(i2A, S2A);
        RCPA(i2B, S2B);
        float c1Af = i1A + i2A,  c2Af = -(i1A * i2A);
        float d3Af = 2.f * i1A * i2A, d4Af = -(i1A * i1A * i2A);
        float c1Bf = i1B + i2B,  c2Bf = -(i1B * i2B);
        float d3Bf = 2.f * i1B * i2B, d4Bf = -(i1B * i1B * i2B);

        {   // sweep row A: khot += c1*a + c2*a^2 ; a = a + a^2*(d2 + d3*a + d4*a^2), d2 = -c1
            const uint64_t c1 = pack2(c1Af, c1Af), c2 = pack2(c2Af, c2Af);
            const uint64_t d2 = pack2(-c1Af, -c1Af), d3 = pack2(d3Af, d3Af), d4 = pack2(d4Af, d4Af);
            uint64_t ps = zero2, qs = zero2;
#pragma unroll
            for (int j = 0; j < PAIRS; j++) {
                uint64_t w, t;
                MUL2(w, aA[j], aA[j]);            // a^2
                FMA2(kA[j], aA[j], c1, kA[j]);    // khot += c1*a
                FMA2(kA[j], w,     c2, kA[j]);    // khot += c2*a^2
                FMA2(t, aA[j], d4, d3);           // d3 + d4*a
                FMA2(t, aA[j], t,  d2);           // d2 + d3*a + d4*a^2
                FMA2(aA[j], w, t, aA[j]);         // a'' = a + a^2*t
                ADD2(ps, ps, aA[j]);              // next P
                FMA2(qs, aA[j], aA[j], qs);       // next Q
            }
            float x0, x1, y0, y1;
            unpack2(ps, x0, x1); unpack2(qs, y0, y1);
            pA = x0 + x1; qA = y0 + y1;
        }
        {   // sweep row B
            const uint64_t c1 = pack2(c1Bf, c1Bf), c2 = pack2(c2Bf, c2Bf);
            const uint64_t d2 = pack2(-c1Bf, -c1Bf), d3 = pack2(d3Bf, d3Bf), d4 = pack2(d4Bf, d4Bf);
            uint64_t ps = zero2, qs = zero2;
#pragma unroll
            for (int j = 0; j < PAIRS; j++) {
                uint64_t w, t;
                MUL2(w, aB[j], aB[j]);
                FMA2(kB[j], aB[j], c1, kB[j]);
                FMA2(kB[j], w,     c2, kB[j]);
                FMA2(t, aB[j], d4, d3);
                FMA2(t, aB[j], t,  d2);
                FMA2(aB[j], w, t, aB[j]);
                ADD2(ps, ps, aB[j]);
                FMA2(qs, aB[j], aB[j], qs);
            }
            float x0, x1, y0, y1;
            unpack2(ps, x0, x1); unpack2(qs, y0, y1);
            pB = x0 + x1; qB = y0 + y1;
        }
    }

    // ---- store khot for both rows ----
    float4* oA4 = reinterpret_cast<float4*>(out + offA);
    float4* oB4 = reinterpret_cast<float4*>(out + offB);
#pragma unroll
    for (int v = 0; v < VPT; v++) {
        float4 r;
        unpack2(kA[2*v+0], r.x, r.y);
        unpack2(kA[2*v+1], r.z, r.w);
        oA4[tid + v * THREADS] = r;
        float4 s;
        unpack2(kB[2*v+0], s.x, s.y);
        unpack2(kB[2*v+1], s.z, s.w);
        oB4[tid + v * THREADS] = s;
    }
}

extern "C" void kernel_launch(void* const* d_in, const int* in_sizes, int n_in,
                              void* d_out, int out_size)
{
    const float* scores = (const float*)d_in[0];
    const float* g      = (const float*)d_in[1];
    float* out          = (float*)d_out;
    const int rows = in_sizes[0] / NCOL;   // 4*2048 = 8192
    subset_op_kernel<<<rows / 2, THREADS>>>(scores, g, out);
}